// round 1
// baseline (speedup 1.0000x reference)
#include <cuda_runtime.h>
#include <cuda_bf16.h>
#include <cstdint>

// ---------------------------------------------------------------------------
// AdaConv fused kernel set.
// Shapes: N=8, CH=512, SD=512, H=W=128, NG=64 groups, CIG=8, 3x3 kernels.
// Input order: style(8,512,4,4) predicted(8,512,128,128) dw_w(4096,512,2,2)
//              dw_b(4096) pk_w(4096,512) pk_b(4096) pb_w(512,512) pb_b(512)
// ---------------------------------------------------------------------------

typedef unsigned long long ull;

__device__ __forceinline__ ull pack2(float lo, float hi) {
    ull r;
    asm("mov.b64 %0, {%1, %2};" : "=l"(r) : "f"(lo), "f"(hi));
    return r;
}
__device__ __forceinline__ void unpack2(ull v, float& lo, float& hi) {
    asm("mov.b64 {%0, %1}, %2;" : "=f"(lo), "=f"(hi) : "l"(v));
}
__device__ __forceinline__ ull fma2(ull a, ull b, ull c) {
    ull d;
    asm("fma.rn.f32x2 %0, %1, %2, %3;" : "=l"(d) : "l"(a), "l"(b), "l"(c));
    return d;
}

// ------------------------- scratch (device globals) ------------------------
__device__ float g_colT[8 * 9 * 2048];     // im2col of style: [n][t][k]
__device__ float g_spool[8 * 512];         // avg-pooled style
__device__ float g_dw[8 * 4096 * 9];       // depthwise kernels [n][oc][t]
__device__ float g_pwkn[8 * 4096];         // pointwise kernels [n][c*8+j]
__device__ float g_pwbias[8 * 512];        // pointwise bias
__device__ float g_weff[8 * 512 * 8 * 9];  // fused W_eff [n][c][i][t]
__device__ float g_mean[8 * 512];
__device__ float g_rstd[8 * 512];

// ------------------------- K1: im2col + avg pool ---------------------------
__global__ void k_prep1(const float* __restrict__ style) {
    int idx = blockIdx.x * blockDim.x + threadIdx.x;
    const int COLT = 8 * 9 * 2048;
    if (idx < COLT) {
        int n = idx / (9 * 2048);
        int r = idx % (9 * 2048);
        int t = r / 2048;
        int k = r % 2048;
        int c = k >> 2, dy = (k >> 1) & 1, dx = k & 1;
        int ty = t / 3, tx = t % 3;
        g_colT[idx] = style[((n * 512 + c) * 4 + (ty + dy)) * 4 + (tx + dx)];
    } else if (idx < COLT + 4096) {
        int j = idx - COLT;
        const float* p = style + (size_t)j * 16;
        float s = 0.f;
#pragma unroll
        for (int q = 0; q < 16; q++) s += p[q];
        g_spool[j] = s * (1.f / 16.f);
    }
}

// ------------------------- K2: pointwise heads -----------------------------
__global__ void k_prep2(const float* __restrict__ pk_w, const float* __restrict__ pk_b,
                        const float* __restrict__ pb_w, const float* __restrict__ pb_b) {
    int idx = blockIdx.x * blockDim.x + threadIdx.x;
    if (idx < 32768) {
        int n = idx >> 12, oc = idx & 4095;
        const float4* w = (const float4*)(pk_w + (size_t)oc * 512);
        const float4* s = (const float4*)(g_spool + n * 512);
        float acc = pk_b[oc];
#pragma unroll 4
        for (int q = 0; q < 128; q++) {
            float4 a = w[q], b = s[q];
            acc += a.x * b.x + a.y * b.y + a.z * b.z + a.w * b.w;
        }
        g_pwkn[idx] = acc;
    } else if (idx < 32768 + 4096) {
        int j = idx - 32768;
        int n = j >> 9, c = j & 511;
        const float4* w = (const float4*)(pb_w + (size_t)c * 512);
        const float4* s = (const float4*)(g_spool + n * 512);
        float acc = pb_b[c];
#pragma unroll 4
        for (int q = 0; q < 128; q++) {
            float4 a = w[q], b = s[q];
            acc += a.x * b.x + a.y * b.y + a.z * b.z + a.w * b.w;
        }
        g_pwbias[j] = acc;
    }
}

// ------------------------- K3: dw GEMM (4096x72, k=2048) -------------------
// block: 288 threads = 32 oc x 9 t; colT chunk staged in shared.
__global__ void __launch_bounds__(288) k_dw(const float* __restrict__ dw_w,
                                            const float* __restrict__ dw_b) {
    __shared__ float s_col[9][516];  // padded stride vs bank conflicts
    int n = blockIdx.x >> 7;
    int ocb = blockIdx.x & 127;
    int tid = threadIdx.x;
    int oc_l = tid / 9, t = tid % 9;
    int oc = ocb * 32 + oc_l;
    const float* wrow = dw_w + (size_t)oc * 2048;
    ull acc = 0ULL;
    for (int kc = 0; kc < 4; kc++) {
        __syncthreads();
        for (int j = tid; j < 9 * 512; j += 288) {
            int tt = j >> 9, kk = j & 511;
            s_col[tt][kk] = g_colT[(n * 9 + tt) * 2048 + kc * 512 + kk];
        }
        __syncthreads();
        const float* wc = wrow + kc * 512;
#pragma unroll 4
        for (int k = 0; k < 512; k += 4) {
            longlong2 w2 = *(const longlong2*)(wc + k);
            longlong2 c2 = *(const longlong2*)(&s_col[t][k]);
            acc = fma2((ull)w2.x, (ull)c2.x, acc);
            acc = fma2((ull)w2.y, (ull)c2.y, acc);
        }
    }
    float lo, hi;
    unpack2(acc, lo, hi);
    g_dw[((size_t)n * 4096 + oc) * 9 + t] = lo + hi + dw_b[oc];
}

// ------------------------- K4: fuse depthwise+pointwise --------------------
__global__ void k_fuse() {
    int idx = blockIdx.x * blockDim.x + threadIdx.x;
    if (idx >= 8 * 512 * 8 * 9) return;
    int t = idx % 9;
    int r = idx / 9;
    int i = r & 7; r >>= 3;
    int c = r & 511;
    int n = r >> 9;
    int g = c >> 3;
    const float* kn = g_pwkn + n * 4096 + c * 8;
    float acc = 0.f;
#pragma unroll
    for (int j = 0; j < 8; j++)
        acc += kn[j] * g_dw[((size_t)n * 4096 + ((g * 8 + j) * 8 + i)) * 9 + t];
    g_weff[idx] = acc;  // layout ((n*512+c)*8+i)*9+t
}

// ------------------------- K5: instance-norm stats -------------------------
__global__ void __launch_bounds__(256) k_stats(const float* __restrict__ pred) {
    int bc = blockIdx.x;  // n*512+c
    const float4* p = (const float4*)(pred + (size_t)bc * 16384);
    int tid = threadIdx.x;
    float s = 0.f, ss = 0.f;
#pragma unroll
    for (int k = 0; k < 16; k++) {
        float4 v = p[tid + k * 256];
        s += v.x + v.y + v.z + v.w;
        ss += v.x * v.x + v.y * v.y + v.z * v.z + v.w * v.w;
    }
#pragma unroll
    for (int o = 16; o; o >>= 1) {
        s += __shfl_xor_sync(~0u, s, o);
        ss += __shfl_xor_sync(~0u, ss, o);
    }
    __shared__ float ws[8], wss[8];
    if ((tid & 31) == 0) { ws[tid >> 5] = s; wss[tid >> 5] = ss; }
    __syncthreads();
    if (tid == 0) {
        float S = 0.f, SS = 0.f;
#pragma unroll
        for (int w = 0; w < 8; w++) { S += ws[w]; SS += wss[w]; }
        float mean = S * (1.f / 16384.f);
        float var = (SS - S * mean) * (1.f / 16383.f);  // ddof=1
        g_mean[bc] = mean;
        g_rstd[bc] = rsqrtf(var + 1e-5f);
    }
}

// ------------------------- K6: main grouped conv ---------------------------
// grid: (16 tiles [2x x 8y], 512 groups), block 128 threads.
// Tile: 64 x 16 output, 8 in-ch / 8 out-ch. Norm folded into weights/bias.
__global__ void __launch_bounds__(128) k_conv(const float* __restrict__ pred,
                                              float* __restrict__ out) {
    __shared__ float s_in[8][18][67];
    __shared__ float2 s_w2[8][8][9];  // [o][i][t], duplicated halves for f32x2
    __shared__ float s_bias[8];
    int gb = blockIdx.y;  // 0..511
    int n = gb >> 6, g = gb & 63;
    int x0 = (blockIdx.x & 1) * 64;
    int y0 = (blockIdx.x >> 1) * 16;
    int tid = threadIdx.x;
    int cbase = n * 512 + g * 8;

    // weights scaled by rstd of the input channel
    for (int idx = tid; idx < 576; idx += 128) {
        int t = idx % 9;
        int r = idx / 9;
        int i = r & 7;
        int o = r >> 3;
        float w = g_weff[((size_t)(cbase + o) * 8 + i) * 9 + t] * g_rstd[cbase + i];
        s_w2[o][i][t] = make_float2(w, w);
    }
    __syncthreads();
    if (tid < 8) {
        int o = tid;
        float b = g_pwbias[cbase + o];
#pragma unroll
        for (int i = 0; i < 8; i++) {
            float m = g_mean[cbase + i];
            float sw = 0.f;
#pragma unroll
            for (int t = 0; t < 9; t++) sw += s_w2[o][i][t].x;
            b -= sw * m;
        }
        s_bias[o] = b;
    }

    // input tile with reflect halo (raw values; norm folded into weights)
    const float* pbase = pred + (size_t)cbase * 16384;
    for (int idx = tid; idx < 8 * 18 * 66; idx += 128) {
        int rx = idx % 66;
        int r = idx / 66;
        int ry = r % 18;
        int i = r / 18;
        int gy = y0 - 1 + ry;
        gy = gy < 0 ? -gy : (gy > 127 ? 254 - gy : gy);
        int gx = x0 - 1 + rx;
        gx = gx < 0 ? -gx : (gx > 127 ? 254 - gx : gx);
        s_in[i][ry][rx] = pbase[(size_t)i * 16384 + gy * 128 + gx];
    }
    __syncthreads();

    int px = tid & 7;   // x octet (8 pixels)
    int py = tid >> 3;  // row
    ull acc[8][4];
#pragma unroll
    for (int o = 0; o < 8; o++)
#pragma unroll
        for (int q = 0; q < 4; q++) acc[o][q] = 0ULL;

#pragma unroll 1
    for (int i = 0; i < 8; i++) {
#pragma unroll
        for (int ky = 0; ky < 3; ky++) {
            const float* rp = &s_in[i][py + ky][px * 8];
            float v[10];
#pragma unroll
            for (int j = 0; j < 10; j++) v[j] = rp[j];
            ull P[9];
#pragma unroll
            for (int j = 0; j < 9; j++) P[j] = pack2(v[j], v[j + 1]);
#pragma unroll
            for (int kx = 0; kx < 3; kx++) {
#pragma unroll
                for (int o = 0; o < 8; o++) {
                    ull w2 = *(const ull*)&s_w2[o][i][ky * 3 + kx];
                    acc[o][0] = fma2(w2, P[kx + 0], acc[o][0]);
                    acc[o][1] = fma2(w2, P[kx + 2], acc[o][1]);
                    acc[o][2] = fma2(w2, P[kx + 4], acc[o][2]);
                    acc[o][3] = fma2(w2, P[kx + 6], acc[o][3]);
                }
            }
        }
    }

    float* obase = out + (size_t)cbase * 16384 + (size_t)(y0 + py) * 128 + x0 + px * 8;
#pragma unroll
    for (int o = 0; o < 8; o++) {
        float b = s_bias[o];
        float u0, u1, u2, u3, u4, u5, u6, u7;
        unpack2(acc[o][0], u0, u1);
        unpack2(acc[o][1], u2, u3);
        unpack2(acc[o][2], u4, u5);
        unpack2(acc[o][3], u6, u7);
        float4 lo = make_float4(u0 + b, u1 + b, u2 + b, u3 + b);
        float4 hi = make_float4(u4 + b, u5 + b, u6 + b, u7 + b);
        *(float4*)(obase + (size_t)o * 16384) = lo;
        *(float4*)(obase + (size_t)o * 16384 + 4) = hi;
    }
}

// ------------------------- launch ------------------------------------------
extern "C" void kernel_launch(void* const* d_in, const int* in_sizes, int n_in,
                              void* d_out, int out_size) {
    const float* style = (const float*)d_in[0];
    const float* predicted = (const float*)d_in[1];
    const float* dw_w = (const float*)d_in[2];
    const float* dw_b = (const float*)d_in[3];
    const float* pk_w = (const float*)d_in[4];
    const float* pk_b = (const float*)d_in[5];
    const float* pb_w = (const float*)d_in[6];
    const float* pb_b = (const float*)d_in[7];
    float* out = (float*)d_out;

    (void)dw_b; (void)in_sizes; (void)n_in; (void)out_size;

    // K1: im2col + pool (147456 + 4096 threads)
    k_prep1<<<(147456 + 4096 + 255) / 256, 256>>>(style);
    // K2: pointwise kernel/bias heads
    k_prep2<<<(32768 + 4096 + 255) / 256, 256>>>(pk_w, pk_b, pb_w, pb_b);
    // K3: depthwise-kernel GEMM
    k_dw<<<1024, 288>>>(dw_w, (const float*)d_in[3]);
    // K4: fuse into effective 3x3 weights
    k_fuse<<<(8 * 512 * 8 * 9 + 255) / 256, 256>>>();
    // K5: instance-norm stats
    k_stats<<<4096, 256>>>(predicted);
    // K6: main conv
    dim3 cgrid(16, 512);
    k_conv<<<cgrid, 128>>>(predicted, out);
}

// round 2
// speedup vs baseline: 1.0008x; 1.0008x over previous
#include <cuda_runtime.h>
#include <cuda_bf16.h>
#include <cstdint>

// ---------------------------------------------------------------------------
// AdaConv fused kernel set (round 2).
// Shapes: N=8, CH=512, SD=512, H=W=128, NG=64 groups, CIG=8, 3x3 kernels.
// Input order: style(8,512,4,4) predicted(8,512,128,128) dw_w(4096,512,2,2)
//              dw_b(4096) pk_w(4096,512) pk_b(4096) pb_w(512,512) pb_b(512)
// ---------------------------------------------------------------------------

typedef unsigned long long ull;

__device__ __forceinline__ ull pack2(float lo, float hi) {
    ull r;
    asm("mov.b64 %0, {%1, %2};" : "=l"(r) : "f"(lo), "f"(hi));
    return r;
}
__device__ __forceinline__ void unpack2(ull v, float& lo, float& hi) {
    asm("mov.b64 {%0, %1}, %2;" : "=f"(lo), "=f"(hi) : "l"(v));
}
__device__ __forceinline__ ull fma2(ull a, ull b, ull c) {
    ull d;
    asm("fma.rn.f32x2 %0, %1, %2, %3;" : "=l"(d) : "l"(a), "l"(b), "l"(c));
    return d;
}

// ------------------------- scratch (device globals) ------------------------
__device__ float g_colT[8 * 9 * 2048];   // im2col of style: [n][t][k]
__device__ float g_spool[8 * 512];       // avg-pooled style
__device__ float g_dw[8 * 4096 * 9];     // depthwise kernels [n][oc][t]
__device__ float g_pwkn[8 * 4096];       // pointwise kernels [n][c*8+j]
__device__ float g_pwbias[8 * 512];      // pointwise bias
__device__ float g_mean[8 * 512];
__device__ float g_rstd[8 * 512];

// ------------------------- K1: im2col + avg pool ---------------------------
__global__ void k_prep1(const float* __restrict__ style) {
    int idx = blockIdx.x * blockDim.x + threadIdx.x;
    const int COLT = 8 * 9 * 2048;
    if (idx < COLT) {
        int n = idx / (9 * 2048);
        int r = idx % (9 * 2048);
        int t = r / 2048;
        int k = r % 2048;
        int c = k >> 2, dy = (k >> 1) & 1, dx = k & 1;
        int ty = t / 3, tx = t % 3;
        g_colT[idx] = style[((n * 512 + c) * 4 + (ty + dy)) * 4 + (tx + dx)];
    } else if (idx < COLT + 4096) {
        int j = idx - COLT;
        const float* p = style + (size_t)j * 16;
        float s = 0.f;
#pragma unroll
        for (int q = 0; q < 16; q++) s += p[q];
        g_spool[j] = s * (1.f / 16.f);
    }
}

// ------------------------- K2: pointwise heads -----------------------------
__global__ void k_prep2(const float* __restrict__ pk_w, const float* __restrict__ pk_b,
                        const float* __restrict__ pb_w, const float* __restrict__ pb_b) {
    int idx = blockIdx.x * blockDim.x + threadIdx.x;
    if (idx < 32768) {
        int n = idx >> 12, oc = idx & 4095;
        const float4* w = (const float4*)(pk_w + (size_t)oc * 512);
        const float4* s = (const float4*)(g_spool + n * 512);
        float acc = pk_b[oc];
#pragma unroll 4
        for (int q = 0; q < 128; q++) {
            float4 a = w[q], b = s[q];
            acc += a.x * b.x + a.y * b.y + a.z * b.z + a.w * b.w;
        }
        g_pwkn[idx] = acc;
    } else if (idx < 32768 + 4096) {
        int j = idx - 32768;
        int n = j >> 9, c = j & 511;
        const float4* w = (const float4*)(pb_w + (size_t)c * 512);
        const float4* s = (const float4*)(g_spool + n * 512);
        float acc = pb_b[c];
#pragma unroll 4
        for (int q = 0; q < 128; q++) {
            float4 a = w[q], b = s[q];
            acc += a.x * b.x + a.y * b.y + a.z * b.z + a.w * b.w;
        }
        g_pwbias[j] = acc;
    }
}

// ------------------------- K3: dw GEMM (4096x72, k=2048) -------------------
__global__ void __launch_bounds__(288) k_dw(const float* __restrict__ dw_w,
                                            const float* __restrict__ dw_b) {
    __shared__ float s_col[9][516];
    int n = blockIdx.x >> 7;
    int ocb = blockIdx.x & 127;
    int tid = threadIdx.x;
    int oc_l = tid / 9, t = tid % 9;
    int oc = ocb * 32 + oc_l;
    const float* wrow = dw_w + (size_t)oc * 2048;
    ull acc = 0ULL;
    for (int kc = 0; kc < 4; kc++) {
        __syncthreads();
        for (int j = tid; j < 9 * 512; j += 288) {
            int tt = j >> 9, kk = j & 511;
            s_col[tt][kk] = g_colT[(n * 9 + tt) * 2048 + kc * 512 + kk];
        }
        __syncthreads();
        const float* wc = wrow + kc * 512;
#pragma unroll 4
        for (int k = 0; k < 512; k += 4) {
            longlong2 w2 = *(const longlong2*)(wc + k);
            longlong2 c2 = *(const longlong2*)(&s_col[t][k]);
            acc = fma2((ull)w2.x, (ull)c2.x, acc);
            acc = fma2((ull)w2.y, (ull)c2.y, acc);
        }
    }
    float lo, hi;
    unpack2(acc, lo, hi);
    g_dw[((size_t)n * 4096 + oc) * 9 + t] = lo + hi + dw_b[oc];
}

// ------------------------- K4: instance-norm stats -------------------------
__global__ void __launch_bounds__(256) k_stats(const float* __restrict__ pred) {
    int bc = blockIdx.x;  // n*512+c
    const float4* p = (const float4*)(pred + (size_t)bc * 16384);
    int tid = threadIdx.x;
    float s = 0.f, ss = 0.f;
#pragma unroll
    for (int k = 0; k < 16; k++) {
        float4 v = p[tid + k * 256];
        s += v.x + v.y + v.z + v.w;
        ss += v.x * v.x + v.y * v.y + v.z * v.z + v.w * v.w;
    }
#pragma unroll
    for (int o = 16; o; o >>= 1) {
        s += __shfl_xor_sync(~0u, s, o);
        ss += __shfl_xor_sync(~0u, ss, o);
    }
    __shared__ float ws[8], wss[8];
    if ((tid & 31) == 0) { ws[tid >> 5] = s; wss[tid >> 5] = ss; }
    __syncthreads();
    if (tid == 0) {
        float S = 0.f, SS = 0.f;
#pragma unroll
        for (int w = 0; w < 8; w++) { S += ws[w]; SS += wss[w]; }
        float mean = S * (1.f / 16384.f);
        float var = (SS - S * mean) * (1.f / 16383.f);  // ddof=1
        g_mean[bc] = mean;
        g_rstd[bc] = rsqrtf(var + 1e-5f);
    }
}

// ------------------------- K5: main grouped conv ---------------------------
// grid: (16 tiles [2x x 8y], 512 (n,g)), block 128 threads.
// Tile: 64 x 16 output, 8 in-ch, 8 out-ch computed as 2 passes of 4.
// Weight fusion (dw x pwkn) + norm fold done in-block.
__global__ void __launch_bounds__(128) k_conv(const float* __restrict__ pred,
                                              float* __restrict__ out) {
    __shared__ float s_in[8][18][68];   // padded: 68*4=272B rows, 16B aligned
    __shared__ float s_dw[64][9];       // dw rows for this group: [j*8+i][t]
    __shared__ float s_kn[64];          // pwkn for this group: [o*8+j]
    __shared__ float2 s_w2[8][8][9];    // fused+scaled weights [o][i][t] (dup)
    __shared__ float s_bias[8];

    int gb = blockIdx.y;  // n*64+g
    int n = gb >> 6, g = gb & 63;
    int x0 = (blockIdx.x & 1) * 64;
    int y0 = (blockIdx.x >> 1) * 16;
    int tid = threadIdx.x;
    int cbase = n * 512 + g * 8;

    // stage 1: load group dw + pwkn
    for (int idx = tid; idx < 576; idx += 128) {
        int t = idx % 9;
        int r = idx / 9;  // j*8+i
        s_dw[r][t] = g_dw[((size_t)n * 4096 + (g * 8 + (r >> 3)) * 8 + (r & 7)) * 9 + t];
    }
    if (tid < 64)
        s_kn[tid] = g_pwkn[n * 4096 + (g * 8 + (tid >> 3)) * 8 + (tid & 7)];
    __syncthreads();

    // stage 2: fuse into W_eff * rstd_i, and load input tile (independent)
    for (int idx = tid; idx < 576; idx += 128) {
        int t = idx % 9;
        int r = idx / 9;
        int i = r & 7;
        int o = r >> 3;
        float acc = 0.f;
#pragma unroll
        for (int j = 0; j < 8; j++) acc += s_kn[o * 8 + j] * s_dw[j * 8 + i][t];
        float w = acc * g_rstd[cbase + i];
        s_w2[o][i][t] = make_float2(w, w);
    }
    const float* pbase = pred + (size_t)cbase * 16384;
    for (int idx = tid; idx < 8 * 18 * 66; idx += 128) {
        int rx = idx % 66;
        int r = idx / 66;
        int ry = r % 18;
        int i = r / 18;
        int gy = y0 - 1 + ry;
        gy = gy < 0 ? -gy : (gy > 127 ? 254 - gy : gy);
        int gx = x0 - 1 + rx;
        gx = gx < 0 ? -gx : (gx > 127 ? 254 - gx : gx);
        s_in[i][ry][rx] = pbase[(size_t)i * 16384 + gy * 128 + gx];
    }
    __syncthreads();

    // stage 3: bias with mean fold (needs s_w2)
    if (tid < 8) {
        int o = tid;
        float b = g_pwbias[cbase + o];
#pragma unroll
        for (int i = 0; i < 8; i++) {
            float m = g_mean[cbase + i];
            float sw = 0.f;
#pragma unroll
            for (int t = 0; t < 9; t++) sw += s_w2[o][i][t].x;
            b -= sw * m;
        }
        s_bias[o] = b;
    }
    __syncthreads();

    int px = tid & 7;   // x octet (8 output pixels)
    int py = tid >> 3;  // output row
    float* obase = out + (size_t)cbase * 16384 + (size_t)(y0 + py) * 128 + x0 + px * 8;

#pragma unroll 1
    for (int oh = 0; oh < 2; oh++) {
        ull acc[4][4];
#pragma unroll
        for (int o = 0; o < 4; o++)
#pragma unroll
            for (int q = 0; q < 4; q++) acc[o][q] = 0ULL;

#pragma unroll 1
        for (int i = 0; i < 8; i++) {
#pragma unroll
            for (int ky = 0; ky < 3; ky++) {
                const float* rp = &s_in[i][py + ky][px * 8];
                float4 a = *(const float4*)rp;
                float4 b = *(const float4*)(rp + 4);
                float v8 = rp[8], v9 = rp[9];
                ull P[9];
                P[0] = pack2(a.x, a.y);
                P[1] = pack2(a.y, a.z);
                P[2] = pack2(a.z, a.w);
                P[3] = pack2(a.w, b.x);
                P[4] = pack2(b.x, b.y);
                P[5] = pack2(b.y, b.z);
                P[6] = pack2(b.z, b.w);
                P[7] = pack2(b.w, v8);
                P[8] = pack2(v8, v9);
#pragma unroll
                for (int kx = 0; kx < 3; kx++) {
#pragma unroll
                    for (int o = 0; o < 4; o++) {
                        ull w2 = *(const ull*)&s_w2[oh * 4 + o][i][ky * 3 + kx];
                        acc[o][0] = fma2(w2, P[kx + 0], acc[o][0]);
                        acc[o][1] = fma2(w2, P[kx + 2], acc[o][1]);
                        acc[o][2] = fma2(w2, P[kx + 4], acc[o][2]);
                        acc[o][3] = fma2(w2, P[kx + 6], acc[o][3]);
                    }
                }
            }
        }

#pragma unroll
        for (int o = 0; o < 4; o++) {
            float b = s_bias[oh * 4 + o];
            float u0, u1, u2, u3, u4, u5, u6, u7;
            unpack2(acc[o][0], u0, u1);
            unpack2(acc[o][1], u2, u3);
            unpack2(acc[o][2], u4, u5);
            unpack2(acc[o][3], u6, u7);
            float4 lo = make_float4(u0 + b, u1 + b, u2 + b, u3 + b);
            float4 hi = make_float4(u4 + b, u5 + b, u6 + b, u7 + b);
            float* op = obase + (size_t)(oh * 4 + o) * 16384;
            *(float4*)op = lo;
            *(float4*)(op + 4) = hi;
        }
    }
}

// ------------------------- launch ------------------------------------------
extern "C" void kernel_launch(void* const* d_in, const int* in_sizes, int n_in,
                              void* d_out, int out_size) {
    const float* style = (const float*)d_in[0];
    const float* predicted = (const float*)d_in[1];
    const float* dw_w = (const float*)d_in[2];
    const float* dw_b = (const float*)d_in[3];
    const float* pk_w = (const float*)d_in[4];
    const float* pk_b = (const float*)d_in[5];
    const float* pb_w = (const float*)d_in[6];
    const float* pb_b = (const float*)d_in[7];
    float* out = (float*)d_out;

    (void)in_sizes; (void)n_in; (void)out_size;

    k_prep1<<<(147456 + 4096 + 255) / 256, 256>>>(style);
    k_prep2<<<(32768 + 4096 + 255) / 256, 256>>>(pk_w, pk_b, pb_w, pb_b);
    k_dw<<<1024, 288>>>(dw_w, dw_b);
    k_stats<<<4096, 256>>>(predicted);
    dim3 cgrid(16, 512);
    k_conv<<<cgrid, 128>>>(predicted, out);
}

// round 3
// speedup vs baseline: 1.0009x; 1.0001x over previous
#include <cuda_runtime.h>
#include <cuda_bf16.h>
#include <cstdint>

// ---------------------------------------------------------------------------
// AdaConv fused kernel set (round 2).
// Shapes: N=8, CH=512, SD=512, H=W=128, NG=64 groups, CIG=8, 3x3 kernels.
// Input order: style(8,512,4,4) predicted(8,512,128,128) dw_w(4096,512,2,2)
//              dw_b(4096) pk_w(4096,512) pk_b(4096) pb_w(512,512) pb_b(512)
// ---------------------------------------------------------------------------

typedef unsigned long long ull;

__device__ __forceinline__ ull pack2(float lo, float hi) {
    ull r;
    asm("mov.b64 %0, {%1, %2};" : "=l"(r) : "f"(lo), "f"(hi));
    return r;
}
__device__ __forceinline__ void unpack2(ull v, float& lo, float& hi) {
    asm("mov.b64 {%0, %1}, %2;" : "=f"(lo), "=f"(hi) : "l"(v));
}
__device__ __forceinline__ ull fma2(ull a, ull b, ull c) {
    ull d;
    asm("fma.rn.f32x2 %0, %1, %2, %3;" : "=l"(d) : "l"(a), "l"(b), "l"(c));
    return d;
}

// ------------------------- scratch (device globals) ------------------------
__device__ float g_colT[8 * 9 * 2048];   // im2col of style: [n][t][k]
__device__ float g_spool[8 * 512];       // avg-pooled style
__device__ float g_dw[8 * 4096 * 9];     // depthwise kernels [n][oc][t]
__device__ float g_pwkn[8 * 4096];       // pointwise kernels [n][c*8+j]
__device__ float g_pwbias[8 * 512];      // pointwise bias
__device__ float g_mean[8 * 512];
__device__ float g_rstd[8 * 512];

// ------------------------- K1: im2col + avg pool ---------------------------
__global__ void k_prep1(const float* __restrict__ style) {
    int idx = blockIdx.x * blockDim.x + threadIdx.x;
    const int COLT = 8 * 9 * 2048;
    if (idx < COLT) {
        int n = idx / (9 * 2048);
        int r = idx % (9 * 2048);
        int t = r / 2048;
        int k = r % 2048;
        int c = k >> 2, dy = (k >> 1) & 1, dx = k & 1;
        int ty = t / 3, tx = t % 3;
        g_colT[idx] = style[((n * 512 + c) * 4 + (ty + dy)) * 4 + (tx + dx)];
    } else if (idx < COLT + 4096) {
        int j = idx - COLT;
        const float* p = style + (size_t)j * 16;
        float s = 0.f;
#pragma unroll
        for (int q = 0; q < 16; q++) s += p[q];
        g_spool[j] = s * (1.f / 16.f);
    }
}

// ------------------------- K2: pointwise heads -----------------------------
__global__ void k_prep2(const float* __restrict__ pk_w, const float* __restrict__ pk_b,
                        const float* __restrict__ pb_w, const float* __restrict__ pb_b) {
    int idx = blockIdx.x * blockDim.x + threadIdx.x;
    if (idx < 32768) {
        int n = idx >> 12, oc = idx & 4095;
        const float4* w = (const float4*)(pk_w + (size_t)oc * 512);
        const float4* s = (const float4*)(g_spool + n * 512);
        float acc = pk_b[oc];
#pragma unroll 4
        for (int q = 0; q < 128; q++) {
            float4 a = w[q], b = s[q];
            acc += a.x * b.x + a.y * b.y + a.z * b.z + a.w * b.w;
        }
        g_pwkn[idx] = acc;
    } else if (idx < 32768 + 4096) {
        int j = idx - 32768;
        int n = j >> 9, c = j & 511;
        const float4* w = (const float4*)(pb_w + (size_t)c * 512);
        const float4* s = (const float4*)(g_spool + n * 512);
        float acc = pb_b[c];
#pragma unroll 4
        for (int q = 0; q < 128; q++) {
            float4 a = w[q], b = s[q];
            acc += a.x * b.x + a.y * b.y + a.z * b.z + a.w * b.w;
        }
        g_pwbias[j] = acc;
    }
}

// ------------------------- K3: dw GEMM (4096x72, k=2048) -------------------
__global__ void __launch_bounds__(288) k_dw(const float* __restrict__ dw_w,
                                            const float* __restrict__ dw_b) {
    __shared__ float s_col[9][516];
    int n = blockIdx.x >> 7;
    int ocb = blockIdx.x & 127;
    int tid = threadIdx.x;
    int oc_l = tid / 9, t = tid % 9;
    int oc = ocb * 32 + oc_l;
    const float* wrow = dw_w + (size_t)oc * 2048;
    ull acc = 0ULL;
    for (int kc = 0; kc < 4; kc++) {
        __syncthreads();
        for (int j = tid; j < 9 * 512; j += 288) {
            int tt = j >> 9, kk = j & 511;
            s_col[tt][kk] = g_colT[(n * 9 + tt) * 2048 + kc * 512 + kk];
        }
        __syncthreads();
        const float* wc = wrow + kc * 512;
#pragma unroll 4
        for (int k = 0; k < 512; k += 4) {
            longlong2 w2 = *(const longlong2*)(wc + k);
            longlong2 c2 = *(const longlong2*)(&s_col[t][k]);
            acc = fma2((ull)w2.x, (ull)c2.x, acc);
            acc = fma2((ull)w2.y, (ull)c2.y, acc);
        }
    }
    float lo, hi;
    unpack2(acc, lo, hi);
    g_dw[((size_t)n * 4096 + oc) * 9 + t] = lo + hi + dw_b[oc];
}

// ------------------------- K4: instance-norm stats -------------------------
__global__ void __launch_bounds__(256) k_stats(const float* __restrict__ pred) {
    int bc = blockIdx.x;  // n*512+c
    const float4* p = (const float4*)(pred + (size_t)bc * 16384);
    int tid = threadIdx.x;
    float s = 0.f, ss = 0.f;
#pragma unroll
    for (int k = 0; k < 16; k++) {
        float4 v = p[tid + k * 256];
        s += v.x + v.y + v.z + v.w;
        ss += v.x * v.x + v.y * v.y + v.z * v.z + v.w * v.w;
    }
#pragma unroll
    for (int o = 16; o; o >>= 1) {
        s += __shfl_xor_sync(~0u, s, o);
        ss += __shfl_xor_sync(~0u, ss, o);
    }
    __shared__ float ws[8], wss[8];
    if ((tid & 31) == 0) { ws[tid >> 5] = s; wss[tid >> 5] = ss; }
    __syncthreads();
    if (tid == 0) {
        float S = 0.f, SS = 0.f;
#pragma unroll
        for (int w = 0; w < 8; w++) { S += ws[w]; SS += wss[w]; }
        float mean = S * (1.f / 16384.f);
        float var = (SS - S * mean) * (1.f / 16383.f);  // ddof=1
        g_mean[bc] = mean;
        g_rstd[bc] = rsqrtf(var + 1e-5f);
    }
}

// ------------------------- K5: main grouped conv ---------------------------
// grid: (16 tiles [2x x 8y], 512 (n,g)), block 128 threads.
// Tile: 64 x 16 output, 8 in-ch, 8 out-ch computed as 2 passes of 4.
// Weight fusion (dw x pwkn) + norm fold done in-block.
__global__ void __launch_bounds__(128) k_conv(const float* __restrict__ pred,
                                              float* __restrict__ out) {
    __shared__ float s_in[8][18][68];   // padded: 68*4=272B rows, 16B aligned
    __shared__ float s_dw[64][9];       // dw rows for this group: [j*8+i][t]
    __shared__ float s_kn[64];          // pwkn for this group: [o*8+j]
    __shared__ float2 s_w2[8][8][9];    // fused+scaled weights [o][i][t] (dup)
    __shared__ float s_bias[8];

    int gb = blockIdx.y;  // n*64+g
    int n = gb >> 6, g = gb & 63;
    int x0 = (blockIdx.x & 1) * 64;
    int y0 = (blockIdx.x >> 1) * 16;
    int tid = threadIdx.x;
    int cbase = n * 512 + g * 8;

    // stage 1: load group dw + pwkn
    for (int idx = tid; idx < 576; idx += 128) {
        int t = idx % 9;
        int r = idx / 9;  // j*8+i
        s_dw[r][t] = g_dw[((size_t)n * 4096 + (g * 8 + (r >> 3)) * 8 + (r & 7)) * 9 + t];
    }
    if (tid < 64)
        s_kn[tid] = g_pwkn[n * 4096 + (g * 8 + (tid >> 3)) * 8 + (tid & 7)];
    __syncthreads();

    // stage 2: fuse into W_eff * rstd_i, and load input tile (independent)
    for (int idx = tid; idx < 576; idx += 128) {
        int t = idx % 9;
        int r = idx / 9;
        int i = r & 7;
        int o = r >> 3;
        float acc = 0.f;
#pragma unroll
        for (int j = 0; j < 8; j++) acc += s_kn[o * 8 + j] * s_dw[j * 8 + i][t];
        float w = acc * g_rstd[cbase + i];
        s_w2[o][i][t] = make_float2(w, w);
    }
    const float* pbase = pred + (size_t)cbase * 16384;
    for (int idx = tid; idx < 8 * 18 * 66; idx += 128) {
        int rx = idx % 66;
        int r = idx / 66;
        int ry = r % 18;
        int i = r / 18;
        int gy = y0 - 1 + ry;
        gy = gy < 0 ? -gy : (gy > 127 ? 254 - gy : gy);
        int gx = x0 - 1 + rx;
        gx = gx < 0 ? -gx : (gx > 127 ? 254 - gx : gx);
        s_in[i][ry][rx] = pbase[(size_t)i * 16384 + gy * 128 + gx];
    }
    __syncthreads();

    // stage 3: bias with mean fold (needs s_w2)
    if (tid < 8) {
        int o = tid;
        float b = g_pwbias[cbase + o];
#pragma unroll
        for (int i = 0; i < 8; i++) {
            float m = g_mean[cbase + i];
            float sw = 0.f;
#pragma unroll
            for (int t = 0; t < 9; t++) sw += s_w2[o][i][t].x;
            b -= sw * m;
        }
        s_bias[o] = b;
    }
    __syncthreads();

    int px = tid & 7;   // x octet (8 output pixels)
    int py = tid >> 3;  // output row
    float* obase = out + (size_t)cbase * 16384 + (size_t)(y0 + py) * 128 + x0 + px * 8;

#pragma unroll 1
    for (int oh = 0; oh < 2; oh++) {
        ull acc[4][4];
#pragma unroll
        for (int o = 0; o < 4; o++)
#pragma unroll
            for (int q = 0; q < 4; q++) acc[o][q] = 0ULL;

#pragma unroll 1
        for (int i = 0; i < 8; i++) {
#pragma unroll
            for (int ky = 0; ky < 3; ky++) {
                const float* rp = &s_in[i][py + ky][px * 8];
                float4 a = *(const float4*)rp;
                float4 b = *(const float4*)(rp + 4);
                float v8 = rp[8], v9 = rp[9];
                ull P[9];
                P[0] = pack2(a.x, a.y);
                P[1] = pack2(a.y, a.z);
                P[2] = pack2(a.z, a.w);
                P[3] = pack2(a.w, b.x);
                P[4] = pack2(b.x, b.y);
                P[5] = pack2(b.y, b.z);
                P[6] = pack2(b.z, b.w);
                P[7] = pack2(b.w, v8);
                P[8] = pack2(v8, v9);
#pragma unroll
                for (int kx = 0; kx < 3; kx++) {
#pragma unroll
                    for (int o = 0; o < 4; o++) {
                        ull w2 = *(const ull*)&s_w2[oh * 4 + o][i][ky * 3 + kx];
                        acc[o][0] = fma2(w2, P[kx + 0], acc[o][0]);
                        acc[o][1] = fma2(w2, P[kx + 2], acc[o][1]);
                        acc[o][2] = fma2(w2, P[kx + 4], acc[o][2]);
                        acc[o][3] = fma2(w2, P[kx + 6], acc[o][3]);
                    }
                }
            }
        }

#pragma unroll
        for (int o = 0; o < 4; o++) {
            float b = s_bias[oh * 4 + o];
            float u0, u1, u2, u3, u4, u5, u6, u7;
            unpack2(acc[o][0], u0, u1);
            unpack2(acc[o][1], u2, u3);
            unpack2(acc[o][2], u4, u5);
            unpack2(acc[o][3], u6, u7);
            float4 lo = make_float4(u0 + b, u1 + b, u2 + b, u3 + b);
            float4 hi = make_float4(u4 + b, u5 + b, u6 + b, u7 + b);
            float* op = obase + (size_t)(oh * 4 + o) * 16384;
            *(float4*)op = lo;
            *(float4*)(op + 4) = hi;
        }
    }
}

// ------------------------- launch ------------------------------------------
extern "C" void kernel_launch(void* const* d_in, const int* in_sizes, int n_in,
                              void* d_out, int out_size) {
    const float* style = (const float*)d_in[0];
    const float* predicted = (const float*)d_in[1];
    const float* dw_w = (const float*)d_in[2];
    const float* dw_b = (const float*)d_in[3];
    const float* pk_w = (const float*)d_in[4];
    const float* pk_b = (const float*)d_in[5];
    const float* pb_w = (const float*)d_in[6];
    const float* pb_b = (const float*)d_in[7];
    float* out = (float*)d_out;

    (void)in_sizes; (void)n_in; (void)out_size;

    k_prep1<<<(147456 + 4096 + 255) / 256, 256>>>(style);
    k_prep2<<<(32768 + 4096 + 255) / 256, 256>>>(pk_w, pk_b, pb_w, pb_b);
    k_dw<<<1024, 288>>>(dw_w, dw_b);
    k_stats<<<4096, 256>>>(predicted);
    dim3 cgrid(16, 512);
    k_conv<<<cgrid, 128>>>(predicted, out);
}

// round 4
// speedup vs baseline: 1.0063x; 1.0054x over previous
#include <cuda_runtime.h>
#include <cuda_bf16.h>
#include <cstdint>

// ---------------------------------------------------------------------------
// AdaConv fused kernel set (round 2).
// Shapes: N=8, CH=512, SD=512, H=W=128, NG=64 groups, CIG=8, 3x3 kernels.
// Input order: style(8,512,4,4) predicted(8,512,128,128) dw_w(4096,512,2,2)
//              dw_b(4096) pk_w(4096,512) pk_b(4096) pb_w(512,512) pb_b(512)
// ---------------------------------------------------------------------------

typedef unsigned long long ull;

__device__ __forceinline__ ull pack2(float lo, float hi) {
    ull r;
    asm("mov.b64 %0, {%1, %2};" : "=l"(r) : "f"(lo), "f"(hi));
    return r;
}
__device__ __forceinline__ void unpack2(ull v, float& lo, float& hi) {
    asm("mov.b64 {%0, %1}, %2;" : "=f"(lo), "=f"(hi) : "l"(v));
}
__device__ __forceinline__ ull fma2(ull a, ull b, ull c) {
    ull d;
    asm("fma.rn.f32x2 %0, %1, %2, %3;" : "=l"(d) : "l"(a), "l"(b), "l"(c));
    return d;
}

// ------------------------- scratch (device globals) ------------------------
__device__ float g_colT[8 * 9 * 2048];   // im2col of style: [n][t][k]
__device__ float g_spool[8 * 512];       // avg-pooled style
__device__ float g_dw[8 * 4096 * 9];     // depthwise kernels [n][oc][t]
__device__ float g_pwkn[8 * 4096];       // pointwise kernels [n][c*8+j]
__device__ float g_pwbias[8 * 512];      // pointwise bias
__device__ float g_mean[8 * 512];
__device__ float g_rstd[8 * 512];

// ------------------------- K1: im2col + avg pool ---------------------------
__global__ void k_prep1(const float* __restrict__ style) {
    int idx = blockIdx.x * blockDim.x + threadIdx.x;
    const int COLT = 8 * 9 * 2048;
    if (idx < COLT) {
        int n = idx / (9 * 2048);
        int r = idx % (9 * 2048);
        int t = r / 2048;
        int k = r % 2048;
        int c = k >> 2, dy = (k >> 1) & 1, dx = k & 1;
        int ty = t / 3, tx = t % 3;
        g_colT[idx] = style[((n * 512 + c) * 4 + (ty + dy)) * 4 + (tx + dx)];
    } else if (idx < COLT + 4096) {
        int j = idx - COLT;
        const float* p = style + (size_t)j * 16;
        float s = 0.f;
#pragma unroll
        for (int q = 0; q < 16; q++) s += p[q];
        g_spool[j] = s * (1.f / 16.f);
    }
}

// ------------------------- K2: pointwise heads -----------------------------
__global__ void k_prep2(const float* __restrict__ pk_w, const float* __restrict__ pk_b,
                        const float* __restrict__ pb_w, const float* __restrict__ pb_b) {
    int idx = blockIdx.x * blockDim.x + threadIdx.x;
    if (idx < 32768) {
        int n = idx >> 12, oc = idx & 4095;
        const float4* w = (const float4*)(pk_w + (size_t)oc * 512);
        const float4* s = (const float4*)(g_spool + n * 512);
        float acc = pk_b[oc];
#pragma unroll 4
        for (int q = 0; q < 128; q++) {
            float4 a = w[q], b = s[q];
            acc += a.x * b.x + a.y * b.y + a.z * b.z + a.w * b.w;
        }
        g_pwkn[idx] = acc;
    } else if (idx < 32768 + 4096) {
        int j = idx - 32768;
        int n = j >> 9, c = j & 511;
        const float4* w = (const float4*)(pb_w + (size_t)c * 512);
        const float4* s = (const float4*)(g_spool + n * 512);
        float acc = pb_b[c];
#pragma unroll 4
        for (int q = 0; q < 128; q++) {
            float4 a = w[q], b = s[q];
            acc += a.x * b.x + a.y * b.y + a.z * b.z + a.w * b.w;
        }
        g_pwbias[j] = acc;
    }
}

// ------------------------- K3: dw GEMM (4096x72, k=2048) -------------------
__global__ void __launch_bounds__(288) k_dw(const float* __restrict__ dw_w,
                                            const float* __restrict__ dw_b) {
    __shared__ float s_col[9][516];
    int n = blockIdx.x >> 7;
    int ocb = blockIdx.x & 127;
    int tid = threadIdx.x;
    int oc_l = tid / 9, t = tid % 9;
    int oc = ocb * 32 + oc_l;
    const float* wrow = dw_w + (size_t)oc * 2048;
    ull acc = 0ULL;
    for (int kc = 0; kc < 4; kc++) {
        __syncthreads();
        for (int j = tid; j < 9 * 512; j += 288) {
            int tt = j >> 9, kk = j & 511;
            s_col[tt][kk] = g_colT[(n * 9 + tt) * 2048 + kc * 512 + kk];
        }
        __syncthreads();
        const float* wc = wrow + kc * 512;
#pragma unroll 4
        for (int k = 0; k < 512; k += 4) {
            longlong2 w2 = *(const longlong2*)(wc + k);
            longlong2 c2 = *(const longlong2*)(&s_col[t][k]);
            acc = fma2((ull)w2.x, (ull)c2.x, acc);
            acc = fma2((ull)w2.y, (ull)c2.y, acc);
        }
    }
    float lo, hi;
    unpack2(acc, lo, hi);
    g_dw[((size_t)n * 4096 + oc) * 9 + t] = lo + hi + dw_b[oc];
}

// ------------------------- K4: instance-norm stats -------------------------
__global__ void __launch_bounds__(256) k_stats(const float* __restrict__ pred) {
    int bc = blockIdx.x;  // n*512+c
    const float4* p = (const float4*)(pred + (size_t)bc * 16384);
    int tid = threadIdx.x;
    float s = 0.f, ss = 0.f;
#pragma unroll
    for (int k = 0; k < 16; k++) {
        float4 v = p[tid + k * 256];
        s += v.x + v.y + v.z + v.w;
        ss += v.x * v.x + v.y * v.y + v.z * v.z + v.w * v.w;
    }
#pragma unroll
    for (int o = 16; o; o >>= 1) {
        s += __shfl_xor_sync(~0u, s, o);
        ss += __shfl_xor_sync(~0u, ss, o);
    }
    __shared__ float ws[8], wss[8];
    if ((tid & 31) == 0) { ws[tid >> 5] = s; wss[tid >> 5] = ss; }
    __syncthreads();
    if (tid == 0) {
        float S = 0.f, SS = 0.f;
#pragma unroll
        for (int w = 0; w < 8; w++) { S += ws[w]; SS += wss[w]; }
        float mean = S * (1.f / 16384.f);
        float var = (SS - S * mean) * (1.f / 16383.f);  // ddof=1
        g_mean[bc] = mean;
        g_rstd[bc] = rsqrtf(var + 1e-5f);
    }
}

// ------------------------- K5: main grouped conv ---------------------------
// grid: (16 tiles [2x x 8y], 512 (n,g)), block 128 threads.
// Tile: 64 x 16 output, 8 in-ch, 8 out-ch computed as 2 passes of 4.
// Weight fusion (dw x pwkn) + norm fold done in-block.
__global__ void __launch_bounds__(128) k_conv(const float* __restrict__ pred,
                                              float* __restrict__ out) {
    __shared__ float s_in[8][18][68];   // padded: 68*4=272B rows, 16B aligned
    __shared__ float s_dw[64][9];       // dw rows for this group: [j*8+i][t]
    __shared__ float s_kn[64];          // pwkn for this group: [o*8+j]
    __shared__ float2 s_w2[8][8][9];    // fused+scaled weights [o][i][t] (dup)
    __shared__ float s_bias[8];

    int gb = blockIdx.y;  // n*64+g
    int n = gb >> 6, g = gb & 63;
    int x0 = (blockIdx.x & 1) * 64;
    int y0 = (blockIdx.x >> 1) * 16;
    int tid = threadIdx.x;
    int cbase = n * 512 + g * 8;

    // stage 1: load group dw + pwkn
    for (int idx = tid; idx < 576; idx += 128) {
        int t = idx % 9;
        int r = idx / 9;  // j*8+i
        s_dw[r][t] = g_dw[((size_t)n * 4096 + (g * 8 + (r >> 3)) * 8 + (r & 7)) * 9 + t];
    }
    if (tid < 64)
        s_kn[tid] = g_pwkn[n * 4096 + (g * 8 + (tid >> 3)) * 8 + (tid & 7)];
    __syncthreads();

    // stage 2: fuse into W_eff * rstd_i, and load input tile (independent)
    for (int idx = tid; idx < 576; idx += 128) {
        int t = idx % 9;
        int r = idx / 9;
        int i = r & 7;
        int o = r >> 3;
        float acc = 0.f;
#pragma unroll
        for (int j = 0; j < 8; j++) acc += s_kn[o * 8 + j] * s_dw[j * 8 + i][t];
        float w = acc * g_rstd[cbase + i];
        s_w2[o][i][t] = make_float2(w, w);
    }
    const float* pbase = pred + (size_t)cbase * 16384;
    for (int idx = tid; idx < 8 * 18 * 66; idx += 128) {
        int rx = idx % 66;
        int r = idx / 66;
        int ry = r % 18;
        int i = r / 18;
        int gy = y0 - 1 + ry;
        gy = gy < 0 ? -gy : (gy > 127 ? 254 - gy : gy);
        int gx = x0 - 1 + rx;
        gx = gx < 0 ? -gx : (gx > 127 ? 254 - gx : gx);
        s_in[i][ry][rx] = pbase[(size_t)i * 16384 + gy * 128 + gx];
    }
    __syncthreads();

    // stage 3: bias with mean fold (needs s_w2)
    if (tid < 8) {
        int o = tid;
        float b = g_pwbias[cbase + o];
#pragma unroll
        for (int i = 0; i < 8; i++) {
            float m = g_mean[cbase + i];
            float sw = 0.f;
#pragma unroll
            for (int t = 0; t < 9; t++) sw += s_w2[o][i][t].x;
            b -= sw * m;
        }
        s_bias[o] = b;
    }
    __syncthreads();

    int px = tid & 7;   // x octet (8 output pixels)
    int py = tid >> 3;  // output row
    float* obase = out + (size_t)cbase * 16384 + (size_t)(y0 + py) * 128 + x0 + px * 8;

#pragma unroll 1
    for (int oh = 0; oh < 2; oh++) {
        ull acc[4][4];
#pragma unroll
        for (int o = 0; o < 4; o++)
#pragma unroll
            for (int q = 0; q < 4; q++) acc[o][q] = 0ULL;

#pragma unroll 1
        for (int i = 0; i < 8; i++) {
#pragma unroll
            for (int ky = 0; ky < 3; ky++) {
                const float* rp = &s_in[i][py + ky][px * 8];
                float4 a = *(const float4*)rp;
                float4 b = *(const float4*)(rp + 4);
                float v8 = rp[8], v9 = rp[9];
                ull P[9];
                P[0] = pack2(a.x, a.y);
                P[1] = pack2(a.y, a.z);
                P[2] = pack2(a.z, a.w);
                P[3] = pack2(a.w, b.x);
                P[4] = pack2(b.x, b.y);
                P[5] = pack2(b.y, b.z);
                P[6] = pack2(b.z, b.w);
                P[7] = pack2(b.w, v8);
                P[8] = pack2(v8, v9);
#pragma unroll
                for (int kx = 0; kx < 3; kx++) {
#pragma unroll
                    for (int o = 0; o < 4; o++) {
                        ull w2 = *(const ull*)&s_w2[oh * 4 + o][i][ky * 3 + kx];
                        acc[o][0] = fma2(w2, P[kx + 0], acc[o][0]);
                        acc[o][1] = fma2(w2, P[kx + 2], acc[o][1]);
                        acc[o][2] = fma2(w2, P[kx + 4], acc[o][2]);
                        acc[o][3] = fma2(w2, P[kx + 6], acc[o][3]);
                    }
                }
            }
        }

#pragma unroll
        for (int o = 0; o < 4; o++) {
            float b = s_bias[oh * 4 + o];
            float u0, u1, u2, u3, u4, u5, u6, u7;
            unpack2(acc[o][0], u0, u1);
            unpack2(acc[o][1], u2, u3);
            unpack2(acc[o][2], u4, u5);
            unpack2(acc[o][3], u6, u7);
            float4 lo = make_float4(u0 + b, u1 + b, u2 + b, u3 + b);
            float4 hi = make_float4(u4 + b, u5 + b, u6 + b, u7 + b);
            float* op = obase + (size_t)(oh * 4 + o) * 16384;
            *(float4*)op = lo;
            *(float4*)(op + 4) = hi;
        }
    }
}

// ------------------------- launch ------------------------------------------
extern "C" void kernel_launch(void* const* d_in, const int* in_sizes, int n_in,
                              void* d_out, int out_size) {
    const float* style = (const float*)d_in[0];
    const float* predicted = (const float*)d_in[1];
    const float* dw_w = (const float*)d_in[2];
    const float* dw_b = (const float*)d_in[3];
    const float* pk_w = (const float*)d_in[4];
    const float* pk_b = (const float*)d_in[5];
    const float* pb_w = (const float*)d_in[6];
    const float* pb_b = (const float*)d_in[7];
    float* out = (float*)d_out;

    (void)in_sizes; (void)n_in; (void)out_size;

    k_prep1<<<(147456 + 4096 + 255) / 256, 256>>>(style);
    k_prep2<<<(32768 + 4096 + 255) / 256, 256>>>(pk_w, pk_b, pb_w, pb_b);
    k_dw<<<1024, 288>>>(dw_w, dw_b);
    k_stats<<<4096, 256>>>(predicted);
    dim3 cgrid(16, 512);
    k_conv<<<cgrid, 128>>>(predicted, out);
}